// round 1
// baseline (speedup 1.0000x reference)
#include <cuda_runtime.h>
#include <math.h>

#define N_SAMPLES   65536
#define N_FRAMES    128
#define NUM_COEFF   6
#define NUM_ACTIVE  7
#define NSER        7        // delay series + 6 coeff series

// ---------------- device scratch (no allocation allowed) ----------------
__device__ float g_y[NSER][N_FRAMES];     // spline knot values
__device__ float g_M[NSER][N_FRAMES];     // spline second derivatives
__device__ float g_vals[N_SAMPLES * 8];   // 7 taps + pad, 32B aligned per sample
__device__ float g_x[N_SAMPLES];          // excitation output
__device__ int   g_z[N_SAMPLES];          // integer delay per sample
__device__ int   g_minz;
__device__ int   g_maxz;
__device__ int   g_flag;                  // nonzero if exc coefficients are nonzero

// ---------------- kernel A: coeff frames + spline tridiagonal solves ----------------
__global__ void prep_kernel(const float* __restrict__ delay,
                            const float* __restrict__ raw_gain,
                            const float* __restrict__ raw_coeff)
{
    __shared__ float s_y[NSER][N_FRAMES];
    __shared__ float s_cp[N_FRAMES];        // Thomas c' (126 used)
    __shared__ float s_d[NSER][N_FRAMES];   // Thomas d' (126 used)
    __shared__ float s_gain;

    const int tid = threadIdx.x;

    if (tid == 0) {
        s_gain = 1.0f / (1.0f + expf(-raw_gain[0]));
        g_minz = 0x7fffffff;
        g_maxz = 0;
        g_flag = 0;
        // c' sequence for tridiag(1,4,1): constant, input-independent
        float c = 0.25f;
        s_cp[0] = c;
        for (int i = 1; i < N_FRAMES - 2; i++) {
            c = 1.0f / (4.0f - c);
            s_cp[i] = c;
        }
    }
    __syncthreads();

    // sigmoid(raw_coeff) into s_y rows 1..6
    for (int i = tid; i < N_FRAMES * NUM_COEFF; i += blockDim.x) {
        int r = i / NUM_COEFF, c = i % NUM_COEFF;
        s_y[1 + c][r] = 1.0f / (1.0f + expf(-raw_coeff[i]));
    }
    for (int r = tid; r < N_FRAMES; r += blockDim.x)
        s_y[0][r] = delay[r];
    __syncthreads();

    // normalize coefficient rows, scale by gain
    for (int r = tid; r < N_FRAMES; r += blockDim.x) {
        float sum = 0.0f;
        #pragma unroll
        for (int c = 0; c < NUM_COEFF; c++) sum += s_y[1 + c][r];
        float scale = s_gain / sum;
        #pragma unroll
        for (int c = 0; c < NUM_COEFF; c++) s_y[1 + c][r] *= scale;
    }
    __syncthreads();

    // Thomas solve (one series per thread): T M_inner = rhs,
    // rhs[i] = 6*(y[i+2]-2y[i+1]+y[i])/h^2, h = 1/127
    if (tid < NSER) {
        const int m = N_FRAMES - 2;   // 126
        const float K = 6.0f * 127.0f * 127.0f;
        float* y = s_y[tid];
        float* d = s_d[tid];

        float dp = K * (y[2] - 2.0f * y[1] + y[0]) * 0.25f;
        d[0] = dp;
        for (int i = 1; i < m; i++) {
            float rhs = K * (y[i + 2] - 2.0f * y[i + 1] + y[i]);
            dp = (rhs - dp) * s_cp[i];
            d[i] = dp;
        }
        g_M[tid][0] = 0.0f;
        g_M[tid][N_FRAMES - 1] = 0.0f;
        float Mn = 0.0f;
        for (int i = m - 1; i >= 0; i--) {
            Mn = d[i] - s_cp[i] * Mn;
            g_M[tid][i + 1] = Mn;
        }
    }
    __syncthreads();

    for (int i = tid; i < NSER * N_FRAMES; i += blockDim.x)
        (&g_y[0][0])[i] = (&s_y[0][0])[i];
}

// ---------------- kernel B: per-sample spline eval + tap weights ----------------
__global__ void sample_kernel(const float* __restrict__ exc,
                              const float* __restrict__ burst)
{
    const int t = blockIdx.x * blockDim.x + threadIdx.x;
    if (t >= N_SAMPLES) return;

    const float tt = (float)t * (1.0f / 65535.0f);
    int idx = (int)floorf(tt * 127.0f);
    idx = max(0, min(idx, 126));
    const float s  = tt - (float)idx * (1.0f / 127.0f);
    const float s2 = s * s;
    const float s3 = s2 * s;

    float vout[NSER];
    #pragma unroll
    for (int c = 0; c < NSER; c++) {
        float yi  = g_y[c][idx];
        float yi1 = g_y[c][idx + 1];
        float Mi  = g_M[c][idx];
        float Mi1 = g_M[c][idx + 1];
        // b = (yi1-yi)/h - h*(2Mi+Mi1)/6 ; val = yi + b*s + Mi*s^2/2 + (Mi1-Mi)*s^3/(6h)
        float bsl = (yi1 - yi) * 127.0f - (2.0f * Mi + Mi1) * (1.0f / 762.0f);
        vout[c] = yi + bsl * s + 0.5f * Mi * s2 + (Mi1 - Mi) * s3 * (127.0f / 6.0f);
    }

    const float delay_i = vout[0];
    const int   z    = (int)floorf(delay_i);
    const float alfa = delay_i - (float)z;
    const float oma  = 1.0f - alfa;

    float v[8];
    v[0] = -oma * vout[1];
    #pragma unroll
    for (int k = 1; k < NUM_COEFF; k++)
        v[k] = -(alfa * vout[k] + oma * vout[k + 1]);
    v[6] = -alfa * vout[NUM_COEFF];
    v[7] = 0.0f;

    #pragma unroll
    for (int k = 0; k < 8; k++) g_vals[t * 8 + k] = v[k];
    g_z[t] = z;
    g_x[t] = burst[t];                 // general-case x overwritten by exc_scan if needed

    if (exc[t] != 0.0f) atomicExch(&g_flag, 1);

    // per-warp reduction for min/max delay
    int wmin = __reduce_min_sync(0xffffffffu, z);
    int wmax = __reduce_max_sync(0xffffffffu, z);
    if ((threadIdx.x & 31) == 0) {
        atomicMin(&g_minz, wmin);
        atomicMax(&g_maxz, wmax);
    }
}

// ---------------- kernel B2: general exc IIR fallback (never taken for these inputs) ----
__global__ void exc_scan_kernel(const float* __restrict__ exc,
                                const float* __restrict__ burst)
{
    if (g_flag) {
        float ym1 = 0.0f;
        for (int t = 0; t < N_SAMPLES; t++) {
            ym1 = burst[t] - exc[t] * ym1;
            g_x[t] = ym1;
        }
    }
}

// ---------------- kernel C: chunk-parallel Karplus-Strong scan ----------------
__global__ void __launch_bounds__(128, 1) ks_kernel(float* __restrict__ out)
{
    __shared__ float ring[1024];
    __shared__ int   sL;

    const int tid = threadIdx.x;
    for (int i = tid; i < 1024; i += 128) ring[i] = 0.0f;

    if (tid == 0) {
        int L = g_minz + 1;                   // dependency lag lower bound
        if (L > 128) L = 128;
        int cap = 1024 - (g_maxz + NUM_ACTIVE); // ring read/write disjointness
        if (L > cap) L = cap;
        if (L < 1)  L = 1;
        sL = L;
    }
    __syncthreads();
    const int L = sL;

    // prefetch chunk 0
    float4 va = {0,0,0,0}, vb = {0,0,0,0};
    float  xv = 0.0f;
    int    zv = 0;
    if (tid < L) {
        va = *reinterpret_cast<const float4*>(&g_vals[tid * 8]);
        vb = *reinterpret_cast<const float4*>(&g_vals[tid * 8 + 4]);
        xv = g_x[tid];
        zv = g_z[tid];
    }

    for (int t0 = 0; t0 < N_SAMPLES; t0 += L) {
        const int  t   = t0 + tid;
        const bool act = (tid < L) && (t < N_SAMPLES);

        float4 ca = va, cb = vb;
        float  cx = xv;
        int    cz = zv;

        // prefetch next chunk (independent of ring; overlaps the barrier/LDS)
        const int tn = t + L;
        if ((tid < L) && tn < N_SAMPLES) {
            va = *reinterpret_cast<const float4*>(&g_vals[tn * 8]);
            vb = *reinterpret_cast<const float4*>(&g_vals[tn * 8 + 4]);
            xv = g_x[tn];
            zv = g_z[tn];
        }

        if (act) {
            const int base = t - 1 - cz;
            float tp0 = (base     >= 0) ? ring[(base    ) & 1023] : 0.0f;
            float tp1 = (base - 1 >= 0) ? ring[(base - 1) & 1023] : 0.0f;
            float tp2 = (base - 2 >= 0) ? ring[(base - 2) & 1023] : 0.0f;
            float tp3 = (base - 3 >= 0) ? ring[(base - 3) & 1023] : 0.0f;
            float tp4 = (base - 4 >= 0) ? ring[(base - 4) & 1023] : 0.0f;
            float tp5 = (base - 5 >= 0) ? ring[(base - 5) & 1023] : 0.0f;
            float tp6 = (base - 6 >= 0) ? ring[(base - 6) & 1023] : 0.0f;

            float a0 = ca.x * tp0 + ca.y * tp1;
            float a1 = ca.z * tp2 + ca.w * tp3;
            float a2 = cb.x * tp4 + cb.y * tp5;
            float a3 = cb.z * tp6;
            float y  = cx - ((a0 + a1) + (a2 + a3));

            out[t] = y;
            ring[t & 1023] = y;   // disjoint from this chunk's read slots (maxlag+L < 1024)
        }
        __syncthreads();
    }
}

// ---------------- launcher ----------------
extern "C" void kernel_launch(void* const* d_in, const int* in_sizes, int n_in,
                              void* d_out, int out_size)
{
    const float* delay     = (const float*)d_in[0];  // [128]
    const float* raw_gain  = (const float*)d_in[1];  // [1]
    const float* raw_coeff = (const float*)d_in[2];  // [128,6]
    const float* exc       = (const float*)d_in[3];  // [1,65536,1]
    const float* burst     = (const float*)d_in[4];  // [65536]
    float* out = (float*)d_out;

    prep_kernel<<<1, 256>>>(delay, raw_gain, raw_coeff);
    sample_kernel<<<N_SAMPLES / 256, 256>>>(exc, burst);
    exc_scan_kernel<<<1, 1>>>(exc, burst);
    ks_kernel<<<1, 128>>>(out);
}

// round 2
// speedup vs baseline: 2.2425x; 2.2425x over previous
#include <cuda_runtime.h>
#include <math.h>

#define N_SAMPLES   65536
#define N_FRAMES    128
#define NUM_COEFF   6
#define NUM_ACTIVE  7
#define NSER        7        // delay series + 6 coeff series

// ---------------- device scratch (no allocation allowed) ----------------
__device__ float  g_y[NSER][N_FRAMES];   // spline knot values
__device__ float  g_M[NSER][N_FRAMES];   // spline second derivatives
__device__ float4 g_A[N_SAMPLES];        // taps v0..v3 (pre-negated)
__device__ float4 g_B[N_SAMPLES];        // taps v4,v5,v6, x
__device__ int    g_P[N_SAMPLES];        // base index = t - 1 - z
__device__ int    g_minz;
__device__ int    g_maxz;
__device__ int    g_flag;                // nonzero if exc coefficients are nonzero

// ---------------- kernel A: coeff frames + spline tridiagonal solves ----------------
__global__ void prep_kernel(const float* __restrict__ delay,
                            const float* __restrict__ raw_gain,
                            const float* __restrict__ raw_coeff)
{
    __shared__ float s_y[NSER][N_FRAMES];
    __shared__ float s_cp[N_FRAMES];        // Thomas c' (126 used)
    __shared__ float s_d[NSER][N_FRAMES];   // Thomas d' (126 used)
    __shared__ float s_gain;

    const int tid = threadIdx.x;

    if (tid == 0) {
        s_gain = 1.0f / (1.0f + expf(-raw_gain[0]));
        g_minz = 0x7fffffff;
        g_maxz = 0;
        g_flag = 0;
        // c' sequence for tridiag(1,4,1): constant, input-independent
        float c = 0.25f;
        s_cp[0] = c;
        for (int i = 1; i < N_FRAMES - 2; i++) {
            c = 1.0f / (4.0f - c);
            s_cp[i] = c;
        }
    }
    __syncthreads();

    // sigmoid(raw_coeff) into s_y rows 1..6
    for (int i = tid; i < N_FRAMES * NUM_COEFF; i += blockDim.x) {
        int r = i / NUM_COEFF, c = i % NUM_COEFF;
        s_y[1 + c][r] = 1.0f / (1.0f + expf(-raw_coeff[i]));
    }
    for (int r = tid; r < N_FRAMES; r += blockDim.x)
        s_y[0][r] = delay[r];
    __syncthreads();

    // normalize coefficient rows, scale by gain
    for (int r = tid; r < N_FRAMES; r += blockDim.x) {
        float sum = 0.0f;
        #pragma unroll
        for (int c = 0; c < NUM_COEFF; c++) sum += s_y[1 + c][r];
        float scale = s_gain / sum;
        #pragma unroll
        for (int c = 0; c < NUM_COEFF; c++) s_y[1 + c][r] *= scale;
    }
    __syncthreads();

    // Thomas solve (one series per thread)
    if (tid < NSER) {
        const int m = N_FRAMES - 2;   // 126
        const float K = 6.0f * 127.0f * 127.0f;
        float* y = s_y[tid];
        float* d = s_d[tid];

        float dp = K * (y[2] - 2.0f * y[1] + y[0]) * 0.25f;
        d[0] = dp;
        for (int i = 1; i < m; i++) {
            float rhs = K * (y[i + 2] - 2.0f * y[i + 1] + y[i]);
            dp = (rhs - dp) * s_cp[i];
            d[i] = dp;
        }
        g_M[tid][0] = 0.0f;
        g_M[tid][N_FRAMES - 1] = 0.0f;
        float Mn = 0.0f;
        for (int i = m - 1; i >= 0; i--) {
            Mn = d[i] - s_cp[i] * Mn;
            g_M[tid][i + 1] = Mn;
        }
    }
    __syncthreads();

    for (int i = tid; i < NSER * N_FRAMES; i += blockDim.x)
        (&g_y[0][0])[i] = (&s_y[0][0])[i];
}

// ---------------- kernel B: per-sample spline eval + tap weights ----------------
__global__ void sample_kernel(const float* __restrict__ exc,
                              const float* __restrict__ burst)
{
    const int t = blockIdx.x * blockDim.x + threadIdx.x;
    if (t >= N_SAMPLES) return;

    const float tt = (float)t * (1.0f / 65535.0f);
    int idx = (int)floorf(tt * 127.0f);
    idx = max(0, min(idx, 126));
    const float s  = tt - (float)idx * (1.0f / 127.0f);
    const float s2 = s * s;
    const float s3 = s2 * s;

    float vout[NSER];
    #pragma unroll
    for (int c = 0; c < NSER; c++) {
        float yi  = g_y[c][idx];
        float yi1 = g_y[c][idx + 1];
        float Mi  = g_M[c][idx];
        float Mi1 = g_M[c][idx + 1];
        float bsl = (yi1 - yi) * 127.0f - (2.0f * Mi + Mi1) * (1.0f / 762.0f);
        vout[c] = yi + bsl * s + 0.5f * Mi * s2 + (Mi1 - Mi) * s3 * (127.0f / 6.0f);
    }

    const float delay_i = vout[0];
    const int   z    = (int)floorf(delay_i);
    const float alfa = delay_i - (float)z;
    const float oma  = 1.0f - alfa;

    float v[7];
    v[0] = -oma * vout[1];
    #pragma unroll
    for (int k = 1; k < NUM_COEFF; k++)
        v[k] = -(alfa * vout[k] + oma * vout[k + 1]);
    v[6] = -alfa * vout[NUM_COEFF];

    g_A[t] = make_float4(v[0], v[1], v[2], v[3]);
    g_B[t] = make_float4(v[4], v[5], v[6], burst[t]);  // .w = x (general case overwritten)
    g_P[t] = t - 1 - z;

    if (exc[t] != 0.0f) atomicExch(&g_flag, 1);

    int wmin = __reduce_min_sync(0xffffffffu, z);
    int wmax = __reduce_max_sync(0xffffffffu, z);
    if ((threadIdx.x & 31) == 0) {
        atomicMin(&g_minz, wmin);
        atomicMax(&g_maxz, wmax);
    }
}

// ---------------- kernel B2: general exc IIR fallback (not taken for these inputs) ----
__global__ void exc_scan_kernel(const float* __restrict__ exc,
                                const float* __restrict__ burst)
{
    if (g_flag) {
        float ym1 = 0.0f;
        for (int t = 0; t < N_SAMPLES; t++) {
            ym1 = burst[t] - exc[t] * ym1;
            g_B[t].w = ym1;
        }
    }
}

// ---------------- kernel C: chunk-parallel Karplus-Strong scan ----------------
// Depth-2 software-pipelined: while computing chunk i, the data for chunk i+2
// is already in flight; loads never sit on the critical path.
// Ring-index safety (no bounds checks needed): reads of y[j], j<0 map to slots
// j+1024 >= 704 which are first written at t >= 704, strictly after the last
// read of any negative index (t <= j + 1 + maxz + 6 < 321).
__global__ void __launch_bounds__(128, 1) ks_kernel(float* __restrict__ out)
{
    __shared__ float ring[1024];
    __shared__ int   sL;

    const int tid = threadIdx.x;
    #pragma unroll
    for (int i = tid; i < 1024; i += 128) ring[i] = 0.0f;

    if (tid == 0) {
        int L = g_minz + 1;                       // dependency lag lower bound
        if (L > 128) L = 128;
        int cap = 1024 - (g_maxz + NUM_ACTIVE) - 1;  // ring disjointness
        if (L > cap) L = cap;
        if (L < 1)  L = 1;
        sL = L;
    }
    __syncthreads();
    const int L   = sL;
    const int LL  = 2 * L;
    const bool on = (tid < L);

    // preload chunks 0 and 1
    float4 A0 = {0,0,0,0}, B0 = {0,0,0,0}; int P0 = 0;
    float4 A1 = {0,0,0,0}, B1 = {0,0,0,0}; int P1 = 0;
    if (on) {
        A0 = g_A[tid];     B0 = g_B[tid];     P0 = g_P[tid];
        A1 = g_A[tid + L]; B1 = g_B[tid + L]; P1 = g_P[tid + L];
    }

    for (int t0 = 0; t0 < N_SAMPLES; t0 += LL) {
        // ---- sub-iteration 0: chunk at t0 ----
        {
            const int t = t0 + tid;
            float4 a = A0, b = B0; const int pb = P0;
            const int tp = t + LL;
            if (on && tp < N_SAMPLES) {
                A0 = g_A[tp]; B0 = g_B[tp]; P0 = g_P[tp];
            }
            if (on && t < N_SAMPLES) {
                float r0 = ring[(pb    ) & 1023];
                float r1 = ring[(pb - 1) & 1023];
                float r2 = ring[(pb - 2) & 1023];
                float r3 = ring[(pb - 3) & 1023];
                float r4 = ring[(pb - 4) & 1023];
                float r5 = ring[(pb - 5) & 1023];
                float r6 = ring[(pb - 6) & 1023];
                float m0 = fmaf(a.x, r0, a.y * r1);
                float m1 = fmaf(a.z, r2, a.w * r3);
                float m2 = fmaf(b.x, r4, b.y * r5);
                float m3 = b.z * r6;
                float y  = b.w - ((m0 + m1) + (m2 + m3));
                ring[t & 1023] = y;
                out[t] = y;
            }
            __syncthreads();
        }
        // ---- sub-iteration 1: chunk at t0 + L ----
        {
            const int t = t0 + L + tid;
            float4 a = A1, b = B1; const int pb = P1;
            const int tp = t + LL;
            if (on && tp < N_SAMPLES) {
                A1 = g_A[tp]; B1 = g_B[tp]; P1 = g_P[tp];
            }
            if (on && t < N_SAMPLES) {
                float r0 = ring[(pb    ) & 1023];
                float r1 = ring[(pb - 1) & 1023];
                float r2 = ring[(pb - 2) & 1023];
                float r3 = ring[(pb - 3) & 1023];
                float r4 = ring[(pb - 4) & 1023];
                float r5 = ring[(pb - 5) & 1023];
                float r6 = ring[(pb - 6) & 1023];
                float m0 = fmaf(a.x, r0, a.y * r1);
                float m1 = fmaf(a.z, r2, a.w * r3);
                float m2 = fmaf(b.x, r4, b.y * r5);
                float m3 = b.z * r6;
                float y  = b.w - ((m0 + m1) + (m2 + m3));
                ring[t & 1023] = y;
                out[t] = y;
            }
            __syncthreads();
        }
    }
}

// ---------------- launcher ----------------
extern "C" void kernel_launch(void* const* d_in, const int* in_sizes, int n_in,
                              void* d_out, int out_size)
{
    const float* delay     = (const float*)d_in[0];  // [128]
    const float* raw_gain  = (const float*)d_in[1];  // [1]
    const float* raw_coeff = (const float*)d_in[2];  // [128,6]
    const float* exc       = (const float*)d_in[3];  // [1,65536,1]
    const float* burst     = (const float*)d_in[4];  // [65536]
    float* out = (float*)d_out;

    prep_kernel<<<1, 256>>>(delay, raw_gain, raw_coeff);
    sample_kernel<<<N_SAMPLES / 256, 256>>>(exc, burst);
    exc_scan_kernel<<<1, 1>>>(exc, burst);
    ks_kernel<<<1, 128>>>(out);
}

// round 3
// speedup vs baseline: 2.9284x; 1.3059x over previous
#include <cuda_runtime.h>
#include <math.h>

#define N_SAMPLES   65536
#define N_FRAMES    128
#define NUM_COEFF   6
#define NUM_ACTIVE  7
#define NSER        7        // delay series + 6 coeff series
#define DEPTH       4        // software pipeline depth in ks_kernel

// ---------------- device scratch (no allocation allowed) ----------------
__device__ float  g_y[NSER][N_FRAMES];   // spline knot values
__device__ float  g_M[NSER][N_FRAMES];   // spline second derivatives
__device__ float4 g_A[N_SAMPLES];        // taps v0..v3 (pre-negated)
__device__ float4 g_B[N_SAMPLES];        // taps v4,v5,v6, x
__device__ int    g_P[N_SAMPLES];        // base index = t - 1 - z
__device__ int    g_minz;
__device__ int    g_maxz;
__device__ int    g_flag;                // nonzero if exc coefficients are nonzero

// ---------------- kernel A: coeff frames + spline tridiagonal solves ----------------
__global__ void prep_kernel(const float* __restrict__ delay,
                            const float* __restrict__ raw_gain,
                            const float* __restrict__ raw_coeff)
{
    __shared__ float s_y[NSER][N_FRAMES];
    __shared__ float s_cp[N_FRAMES];        // Thomas c' (126 used)
    __shared__ float s_d[NSER][N_FRAMES];   // Thomas d' (126 used)
    __shared__ float s_gain;

    const int tid = threadIdx.x;

    if (tid == 0) {
        s_gain = 1.0f / (1.0f + expf(-raw_gain[0]));
        g_minz = 0x7fffffff;
        g_maxz = 0;
        g_flag = 0;
        float c = 0.25f;
        s_cp[0] = c;
        for (int i = 1; i < N_FRAMES - 2; i++) {
            c = 1.0f / (4.0f - c);
            s_cp[i] = c;
        }
    }
    __syncthreads();

    for (int i = tid; i < N_FRAMES * NUM_COEFF; i += blockDim.x) {
        int r = i / NUM_COEFF, c = i % NUM_COEFF;
        s_y[1 + c][r] = 1.0f / (1.0f + expf(-raw_coeff[i]));
    }
    for (int r = tid; r < N_FRAMES; r += blockDim.x)
        s_y[0][r] = delay[r];
    __syncthreads();

    for (int r = tid; r < N_FRAMES; r += blockDim.x) {
        float sum = 0.0f;
        #pragma unroll
        for (int c = 0; c < NUM_COEFF; c++) sum += s_y[1 + c][r];
        float scale = s_gain / sum;
        #pragma unroll
        for (int c = 0; c < NUM_COEFF; c++) s_y[1 + c][r] *= scale;
    }
    __syncthreads();

    // Thomas solve (one series per thread)
    if (tid < NSER) {
        const int m = N_FRAMES - 2;   // 126
        const float K = 6.0f * 127.0f * 127.0f;
        float* y = s_y[tid];
        float* d = s_d[tid];

        float dp = K * (y[2] - 2.0f * y[1] + y[0]) * 0.25f;
        d[0] = dp;
        for (int i = 1; i < m; i++) {
            float rhs = K * (y[i + 2] - 2.0f * y[i + 1] + y[i]);
            dp = (rhs - dp) * s_cp[i];
            d[i] = dp;
        }
        g_M[tid][0] = 0.0f;
        g_M[tid][N_FRAMES - 1] = 0.0f;
        float Mn = 0.0f;
        for (int i = m - 1; i >= 0; i--) {
            Mn = d[i] - s_cp[i] * Mn;
            g_M[tid][i + 1] = Mn;
        }
    }
    __syncthreads();

    for (int i = tid; i < NSER * N_FRAMES; i += blockDim.x)
        (&g_y[0][0])[i] = (&s_y[0][0])[i];
}

// ---------------- kernel B: per-sample spline eval + tap weights ----------------
__global__ void sample_kernel(const float* __restrict__ exc,
                              const float* __restrict__ burst)
{
    const int t = blockIdx.x * blockDim.x + threadIdx.x;
    if (t >= N_SAMPLES) return;

    const float tt = (float)t * (1.0f / 65535.0f);
    int idx = (int)floorf(tt * 127.0f);
    idx = max(0, min(idx, 126));
    const float s  = tt - (float)idx * (1.0f / 127.0f);
    const float s2 = s * s;
    const float s3 = s2 * s;

    float vout[NSER];
    #pragma unroll
    for (int c = 0; c < NSER; c++) {
        float yi  = g_y[c][idx];
        float yi1 = g_y[c][idx + 1];
        float Mi  = g_M[c][idx];
        float Mi1 = g_M[c][idx + 1];
        float bsl = (yi1 - yi) * 127.0f - (2.0f * Mi + Mi1) * (1.0f / 762.0f);
        vout[c] = yi + bsl * s + 0.5f * Mi * s2 + (Mi1 - Mi) * s3 * (127.0f / 6.0f);
    }

    const float delay_i = vout[0];
    const int   z    = (int)floorf(delay_i);
    const float alfa = delay_i - (float)z;
    const float oma  = 1.0f - alfa;

    float v[7];
    v[0] = -oma * vout[1];
    #pragma unroll
    for (int k = 1; k < NUM_COEFF; k++)
        v[k] = -(alfa * vout[k] + oma * vout[k + 1]);
    v[6] = -alfa * vout[NUM_COEFF];

    g_A[t] = make_float4(v[0], v[1], v[2], v[3]);
    g_B[t] = make_float4(v[4], v[5], v[6], burst[t]);  // .w = x (general case overwritten)
    g_P[t] = t - 1 - z;

    if (exc[t] != 0.0f) atomicExch(&g_flag, 1);

    int wmin = __reduce_min_sync(0xffffffffu, z);
    int wmax = __reduce_max_sync(0xffffffffu, z);
    if ((threadIdx.x & 31) == 0) {
        atomicMin(&g_minz, wmin);
        atomicMax(&g_maxz, wmax);
    }
}

// ---------------- kernel B2: general exc IIR fallback (not taken for these inputs) ----
__global__ void exc_scan_kernel(const float* __restrict__ exc,
                                const float* __restrict__ burst)
{
    if (g_flag) {
        float ym1 = 0.0f;
        for (int t = 0; t < N_SAMPLES; t++) {
            ym1 = burst[t] - exc[t] * ym1;
            g_B[t].w = ym1;
        }
    }
}

// ---------------- kernel C: chunk-parallel Karplus-Strong scan ----------------
// Depth-4 software pipeline: data for chunk i+4 is issued while computing
// chunk i, so even at the ~150-cycle iteration floor the load slack
// (~600 cycles) covers DRAM-tier latency.
// Ring-index safety (no bounds checks): reads of y[j], j<0 map to slots
// j+1024 >= 704 which are first written at t >= 704, strictly after the last
// read of any negative index.
__global__ void __launch_bounds__(128, 1) ks_kernel(float* __restrict__ out)
{
    __shared__ float ring[1024];
    __shared__ int   sL;

    const int tid = threadIdx.x;
    #pragma unroll
    for (int i = tid; i < 1024; i += 128) ring[i] = 0.0f;

    if (tid == 0) {
        int L = g_minz + 1;                          // dependency lag bound
        if (L > 128) L = 128;
        int cap = 1024 - (g_maxz + NUM_ACTIVE) - 1;  // ring disjointness
        if (L > cap) L = cap;
        if (L < 1)  L = 1;
        sL = L;
    }
    __syncthreads();
    const int  L  = sL;
    const int  LD = DEPTH * L;
    const bool on = (tid < L);

    float4 A[DEPTH], B[DEPTH];
    int    P[DEPTH];
    #pragma unroll
    for (int s = 0; s < DEPTH; s++) {
        A[s] = make_float4(0, 0, 0, 0);
        B[s] = make_float4(0, 0, 0, 0);
        P[s] = 0;
        if (on) {   // tid + 3L < 65536 always
            A[s] = g_A[tid + s * L];
            B[s] = g_B[tid + s * L];
            P[s] = g_P[tid + s * L];
        }
    }

    for (int t0 = 0; t0 < N_SAMPLES; t0 += LD) {
        #pragma unroll
        for (int s = 0; s < DEPTH; s++) {
            const int t = t0 + s * L + tid;
            float4 a = A[s], b = B[s];
            const int pb = P[s];

            const int tp = t + LD;                   // prefetch DEPTH chunks ahead
            if (on && tp < N_SAMPLES) {
                A[s] = g_A[tp]; B[s] = g_B[tp]; P[s] = g_P[tp];
            }

            if (on && t < N_SAMPLES) {
                float r0 = ring[(pb    ) & 1023];
                float r1 = ring[(pb - 1) & 1023];
                float r2 = ring[(pb - 2) & 1023];
                float r3 = ring[(pb - 3) & 1023];
                float r4 = ring[(pb - 4) & 1023];
                float r5 = ring[(pb - 5) & 1023];
                float r6 = ring[(pb - 6) & 1023];
                float m0 = fmaf(a.x, r0, a.y * r1);
                float m1 = fmaf(a.z, r2, a.w * r3);
                float m2 = fmaf(b.x, r4, b.y * r5);
                float m3 = b.z * r6;
                float y  = b.w - ((m0 + m1) + (m2 + m3));
                ring[t & 1023] = y;
                out[t] = y;
            }
            __syncthreads();
        }
    }
}

// ---------------- launcher ----------------
extern "C" void kernel_launch(void* const* d_in, const int* in_sizes, int n_in,
                              void* d_out, int out_size)
{
    const float* delay     = (const float*)d_in[0];  // [128]
    const float* raw_gain  = (const float*)d_in[1];  // [1]
    const float* raw_coeff = (const float*)d_in[2];  // [128,6]
    const float* exc       = (const float*)d_in[3];  // [1,65536,1]
    const float* burst     = (const float*)d_in[4];  // [65536]
    float* out = (float*)d_out;

    prep_kernel<<<1, 256>>>(delay, raw_gain, raw_coeff);
    sample_kernel<<<N_SAMPLES / 256, 256>>>(exc, burst);
    exc_scan_kernel<<<1, 1>>>(exc, burst);
    ks_kernel<<<1, 128>>>(out);
}